// round 14
// baseline (speedup 1.0000x reference)
#include <cuda_runtime.h>
#include <cuda_fp16.h>
#include <cstdint>

#define TOTAL_ELEMS 33554432

__device__ __align__(128) float g_acc[TOTAL_ELEMS];
__device__ __align__(128) __half g_xhi[TOTAL_ELEMS];
__device__ __align__(128) __half g_whi[3342336];

// ---- image GEMM stage: A 128x144B | B 128x144B (BK=64) ----
#define APITCH 144
#define B_OFF  18432
#define STAGE_B 36864
#define DYN_SMEM (3 * STAGE_B)      // 110592; 2 CTAs/SM

// ---- patch stage: A 256x80B | B 64x80B (BK=32), 4 stages ----
#define PF_BOFF 20480
#define PF_STG  25600
#define PF_DYN  (4 * PF_STG)        // 102400; 2 CTAs/SM

#define CS_PITCH 133

__device__ __forceinline__ uint32_t smem_u32(const void* p) {
    uint32_t a;
    asm("{ .reg .u64 t; cvta.to.shared.u64 t, %1; cvt.u32.u64 %0, t; }" : "=r"(a) : "l"(p));
    return a;
}
__device__ __forceinline__ void ldsm4(uint32_t* r, uint32_t a) {
    asm volatile("ldmatrix.sync.aligned.m8n8.x4.shared.b16 {%0,%1,%2,%3}, [%4];"
        : "=r"(r[0]), "=r"(r[1]), "=r"(r[2]), "=r"(r[3]) : "r"(a));
}
__device__ __forceinline__ void mma16816(float* d, const uint32_t* a, const uint32_t* b) {
    asm volatile("mma.sync.aligned.m16n8k16.row.col.f32.f16.f16.f32 "
        "{%0,%1,%2,%3}, {%4,%5,%6,%7}, {%8,%9}, {%0,%1,%2,%3};"
        : "+f"(d[0]), "+f"(d[1]), "+f"(d[2]), "+f"(d[3])
        : "r"(a[0]), "r"(a[1]), "r"(a[2]), "r"(a[3]), "r"(b[0]), "r"(b[1]));
}
__device__ __forceinline__ void cpa16(uint32_t s, const void* g) {
    asm volatile("cp.async.cg.shared.global [%0], [%1], 16;" :: "r"(s), "l"(g));
}
__device__ __forceinline__ void red_add(float* p, float v) {
    asm volatile("red.global.add.f32 [%0], %1;" :: "l"(p), "f"(v) : "memory");
}
__device__ __forceinline__ void l2pf(const void* p) {
    asm volatile("prefetch.global.L2 [%0];" :: "l"(p));
}
#define CPA_COMMIT() asm volatile("cp.async.commit_group;" ::: "memory")
#define CPA_WAITG(k) asm volatile("cp.async.wait_group %0;" :: "n"(k) : "memory")

// ========= prep_all: CTAs 0..8191 = X->fp16 permute; 8192.. = W->fp16 =========
__global__ __launch_bounds__(256) void prep_all(
    const float* __restrict__ X,
    const float* __restrict__ w_d, const float* __restrict__ w_h,
    const float* __restrict__ w_w, const float* __restrict__ w_pd,
    const float* __restrict__ w_ph, const float* __restrict__ w_pw)
{
    const int t = threadIdx.x;
    if (blockIdx.x < 8192) {
        __shared__ float ts[64][65];
        const int b = blockIdx.x >> 12, sblk = blockIdx.x & 4095;
        const size_t s0 = (size_t)sblk * 64;
        const int sl = t & 63, ch = t >> 6;
        const float* xp = X + (size_t)b * 64 * 262144 + s0;
        #pragma unroll
        for (int i = 0; i < 16; i++) {
            const int c = ch + i * 4;
            ts[sl][c] = xp[(size_t)c * 262144 + sl];
        }
        __syncthreads();
        const int srow = t >> 2, sub = t & 3;
        const size_t row = (size_t)b * 262144 + s0 + srow;
        __half* hp = g_xhi + row * 64 + sub * 16;
        #pragma unroll
        for (int j = 0; j < 16; j++)
            hp[j] = __float2half(ts[srow][sub * 16 + j]);
    } else {
        const int b = blockIdx.x - 8192;
        const float* W; int woff, n, row;
        if (b < 3072) {
            const int op = b >> 10; row = b & 1023; n = 1024; woff = op * 1048576;
            W = (op == 0) ? w_d : (op == 1) ? w_h : w_w;
        } else {
            const int u = b - 3072;
            const int op = u >> 8; row = u & 255; n = 256; woff = 3145728 + op * 65536;
            W = (op == 0) ? w_pd : (op == 1) ? w_ph : w_pw;
        }
        const float* wp = W + (size_t)row * n;
        __half* hp = g_whi + woff + (size_t)row * n;
        for (int c = t; c < n; c += 256)
            hp[c] = __float2half(wp[c]);
    }
}

// ========== patch_fused: 3 patch ops, 256m x 64n, K=768, plain stores to g_acc ==========
__global__ __launch_bounds__(256, 2)
void patch_fused(const float* __restrict__ b_pd, const float* __restrict__ b_ph,
                 const float* __restrict__ b_pw)
{
    extern __shared__ __align__(16) char dsm[];
    __shared__ int base_sh[256];
    __shared__ float bias_sh[64];
    __shared__ int c0_s[3], step_s[3];
    __shared__ long wb_s[3];

    const int tid = threadIdx.x, lane = tid & 31, wid = tid >> 5;
    const int pqr = blockIdx.x, j2 = blockIdx.y;
    const int p = pqr >> 4, q = (pqr >> 2) & 3, r = pqr & 3;

    base_sh[tid] = (tid >> 7) * 262144 + (j2 * 128 + (tid & 127)) * 64;
    if (tid < 64)
        bias_sh[tid] = __ldg(b_pd + p * 64 + tid) + __ldg(b_ph + q * 64 + tid)
                     + __ldg(b_pw + r * 64 + tid);
    if (tid == 0) {
        c0_s[0] = q * 4 + r;      step_s[0] = 16;
        c0_s[1] = p * 16 + r;     step_s[1] = 4;
        c0_s[2] = p * 16 + q * 4; step_s[2] = 1;
        wb_s[0] = (long)(3145728 + p * 16384) * 2;
        wb_s[1] = (long)(3211264 + q * 16384) * 2;
        wb_s[2] = (long)(3276800 + r * 16384) * 2;
    }
    __syncthreads();

    const uint32_t sb = smem_u32(dsm);
    const int myrow = base_sh[tid];
    const uint32_t aSm = (uint32_t)(tid * 80);
    const uint32_t bSm = (uint32_t)(PF_BOFF + (tid >> 2) * 80 + (tid & 3) * 16);
    const long bRow = (long)(tid >> 2) * 512 + (tid & 3) * 16;

    auto issue = [&](int ck) {
        const int op = ck >> 3, s32 = ck & 7, s = s32 >> 1, half = s32 & 1;
        const uint32_t st = sb + (uint32_t)((ck & 3) * PF_STG);
        const char* ga = (const char*)g_xhi
            + ((size_t)(myrow + c0_s[op] + s * step_s[op])) * 128 + half * 64;
        cpa16(st + aSm,      ga);
        cpa16(st + aSm + 16, ga + 16);
        cpa16(st + aSm + 32, ga + 32);
        cpa16(st + aSm + 48, ga + 48);
        const char* gb = (const char*)g_whi + wb_s[op] + bRow + s * 128 + half * 64;
        cpa16(st + bSm, gb);
    };

    const uint32_t a_lm = (uint32_t)((wid * 32 + (lane & 15)) * 80 + (lane >> 4) * 16);
    const uint32_t b_lm = (uint32_t)(PF_BOFF
        + (((lane >> 4) & 1) * 8 + (lane & 7)) * 80 + ((lane >> 3) & 1) * 16);

    float acc[2][8][4];
    #pragma unroll
    for (int i = 0; i < 2; i++)
        #pragma unroll
        for (int j = 0; j < 8; j++)
            #pragma unroll
            for (int u = 0; u < 4; u++) acc[i][j][u] = 0.f;

    issue(0); CPA_COMMIT();
    issue(1); CPA_COMMIT();
    issue(2); CPA_COMMIT();

    for (int ck = 0; ck < 24; ck++) {
        if (ck + 1 < 24) CPA_WAITG(2); else CPA_WAITG(0);
        __syncthreads();
        if (ck + 3 < 24) { issue(ck + 3); CPA_COMMIT(); }

        const uint32_t st = sb + (uint32_t)((ck & 3) * PF_STG);
        #pragma unroll
        for (int ks = 0; ks < 2; ks++) {
            const uint32_t ko = (uint32_t)(ks * 32);
            uint32_t ah[2][4], br[4];
            ldsm4(ah[0], st + a_lm + ko);
            ldsm4(ah[1], st + a_lm + 16 * 80 + ko);
            #pragma unroll
            for (int ntp = 0; ntp < 4; ntp++) {
                ldsm4(br, st + b_lm + ntp * 16 * 80 + ko);
                mma16816(acc[0][2*ntp],   ah[0], br);
                mma16816(acc[0][2*ntp+1], ah[0], br + 2);
                mma16816(acc[1][2*ntp],   ah[1], br);
                mma16816(acc[1][2*ntp+1], ah[1], br + 2);
            }
        }
    }

    {
        const int r0 = lane >> 2, cp = (lane & 3) * 2;
        #pragma unroll
        for (int mt = 0; mt < 2; mt++) {
            const int m0 = wid * 32 + mt * 16 + r0;
            const size_t o0 = ((size_t)(base_sh[m0]     + pqr)) * 64;
            const size_t o1 = ((size_t)(base_sh[m0 + 8] + pqr)) * 64;
            #pragma unroll
            for (int nt = 0; nt < 8; nt++) {
                const int c = nt * 8 + cp;
                const float bx = bias_sh[c], by = bias_sh[c + 1];
                *(float2*)(g_acc + o0 + c) = make_float2(acc[mt][nt][0] + bx,
                                                         acc[mt][nt][1] + by);
                *(float2*)(g_acc + o1 + c) = make_float2(acc[mt][nt][2] + bx,
                                                         acc[mt][nt][3] + by);
            }
        }
    }
}

// ===== images d (0..2047) + h (2048..4095): 128m x 128n BK=64, red.add epilogue =====
__global__ __launch_bounds__(256, 2)
void images_dh(const float* __restrict__ b_d, const float* __restrict__ b_h)
{
    extern __shared__ __align__(16) char dsm[];
    __shared__ int base_sh[128];

    const int tid = threadIdx.x, lane = tid & 31, wid = tid >> 5;
    const uint32_t sb = smem_u32(dsm);
    const int bi = blockIdx.x;
    const int op = bi >> 11, tt = bi & 2047;
    const int nb = tt & 7, bx = tt >> 3;
    const int wm = wid & 3, wn = wid >> 2;
    const int woff = op ? 1048576 : 0;
    const int str_sp = op ? 1024 : 16384;
    const float* Bias = op ? b_h : b_d;

    if (tid < 128) {
        const int m = bx * 128 + tid;
        base_sh[tid] = op
            ? ((m & 1023) + ((m >> 10) & 15) * 16384 + (m >> 14) * 262144)
            : ((m & 16383) + (m >> 14) * 262144);
    }
    __syncthreads();

    const int row = tid >> 1;
    const int half = (tid & 1) * 64;
    const int aBase = base_sh[row];
    const char* aP = (const char*)g_xhi;
    const char* bP = (const char*)(g_whi + woff) + ((size_t)(nb * 128 + row)) * 2048 + half;
    const uint32_t rSm = (uint32_t)(row * APITCH + half);

    auto issue = [&](int ck) {
        const uint32_t st = sb + (uint32_t)((ck % 3) * STAGE_B);
        const size_t aoff = ((size_t)(aBase + ck * str_sp)) * 128 + half;
        cpa16(st + rSm,      aP + aoff);
        cpa16(st + rSm + 16, aP + aoff + 16);
        cpa16(st + rSm + 32, aP + aoff + 32);
        cpa16(st + rSm + 48, aP + aoff + 48);
        const size_t boff = (size_t)ck * 128;
        cpa16(st + B_OFF + rSm,      bP + boff);
        cpa16(st + B_OFF + rSm + 16, bP + boff + 16);
        cpa16(st + B_OFF + rSm + 32, bP + boff + 32);
        cpa16(st + B_OFF + rSm + 48, bP + boff + 48);
    };

    const uint32_t a_lm = (uint32_t)((wm * 32 + (lane & 15)) * APITCH + (lane >> 4) * 16);
    const uint32_t b_lm = (uint32_t)(B_OFF
        + (wn * 64 + ((lane >> 4) & 1) * 8 + (lane & 7)) * APITCH + ((lane >> 3) & 1) * 16);

    float acc[2][8][4];
    #pragma unroll
    for (int i = 0; i < 2; i++)
        #pragma unroll
        for (int j = 0; j < 8; j++)
            #pragma unroll
            for (int q = 0; q < 4; q++) acc[i][j][q] = 0.f;

    issue(0); CPA_COMMIT();
    issue(1); CPA_COMMIT();

    for (int ck = 0; ck < 16; ck++) {
        if (ck + 1 < 16) CPA_WAITG(1); else CPA_WAITG(0);
        __syncthreads();
        if (ck + 2 < 16) { issue(ck + 2); CPA_COMMIT(); }

        const uint32_t st = sb + (uint32_t)((ck % 3) * STAGE_B);
        #pragma unroll
        for (int ks = 0; ks < 4; ks++) {
            const uint32_t ko = (uint32_t)(ks * 32);
            uint32_t ah[2][4], br[4];
            ldsm4(ah[0], st + a_lm + ko);
            ldsm4(ah[1], st + a_lm + 16 * APITCH + ko);
            #pragma unroll
            for (int ntp = 0; ntp < 4; ntp++) {
                ldsm4(br, st + b_lm + ntp * 16 * APITCH + ko);
                mma16816(acc[0][2*ntp],   ah[0], br);
                mma16816(acc[0][2*ntp+1], ah[0], br + 2);
                mma16816(acc[1][2*ntp],   ah[1], br);
                mma16816(acc[1][2*ntp+1], ah[1], br + 2);
            }
        }
    }

    {
        const int s_out = nb * 2 + wn;
        const int r0 = lane >> 2, cp = (lane & 3) * 2;
        #pragma unroll
        for (int mt = 0; mt < 2; mt++) {
            const int ml = wm * 32 + mt * 16 + r0;
            const size_t row0 = (size_t)(base_sh[ml]     + s_out * str_sp);
            const size_t row1 = (size_t)(base_sh[ml + 8] + s_out * str_sp);
            #pragma unroll
            for (int nt = 0; nt < 8; nt++) {
                const int o = nb * 128 + wn * 64 + nt * 8 + cp;
                const int c = nt * 8 + cp;
                const float2 bv = __ldg((const float2*)(Bias + o));
                red_add(g_acc + row0 * 64 + c,     acc[mt][nt][0] + bv.x);
                red_add(g_acc + row0 * 64 + c + 1, acc[mt][nt][1] + bv.y);
                red_add(g_acc + row1 * 64 + c,     acc[mt][nt][2] + bv.x);
                red_add(g_acc + row1 * 64 + c + 1, acc[mt][nt][3] + bv.y);
            }
        }
    }
}

// ==== image op w + final: reads g_acc, adds own result+bias, leaky+residual -> Y ====
__global__ __launch_bounds__(256, 2)
void image_w_final(const float* __restrict__ X, float* __restrict__ Y,
                   const float* __restrict__ b_w)
{
    extern __shared__ __align__(16) char dsm[];
    __shared__ int base_s[128];
    __shared__ float bias_s[128];

    const int tid = threadIdx.x;
    const int lane = tid & 31, wid = tid >> 5;
    const int nb = blockIdx.x, bx = blockIdx.y;
    const int wm = wid & 3, wn = wid >> 2;
    const uint32_t sb = smem_u32(dsm);

    if (tid < 128) {
        const int m = bx * 128 + tid;
        base_s[tid] = (m & 63) + ((m >> 6) & 15) * 1024
                    + ((m >> 10) & 15) * 16384 + (m >> 14) * 262144;
        bias_s[tid] = __ldg(b_w + (nb * 2 + (tid >> 6)) * 64 + (tid & 63));
    }
    __syncthreads();

    const int row = tid >> 1;
    const int half = (tid & 1) * 64;
    const int aBase = base_s[row];
    const char* aP = (const char*)g_xhi;
    const char* bP = (const char*)(g_whi + 2097152) + ((size_t)(nb * 128 + row)) * 2048 + half;
    const uint32_t rSm = (uint32_t)(row * APITCH + half);

    auto issue = [&](int ck) {
        const uint32_t st = sb + (uint32_t)((ck % 3) * STAGE_B);
        const size_t aoff = ((size_t)(aBase + ck * 64)) * 128 + half;
        cpa16(st + rSm,      aP + aoff);
        cpa16(st + rSm + 16, aP + aoff + 16);
        cpa16(st + rSm + 32, aP + aoff + 32);
        cpa16(st + rSm + 48, aP + aoff + 48);
        const size_t boff = (size_t)ck * 128;
        cpa16(st + B_OFF + rSm,      bP + boff);
        cpa16(st + B_OFF + rSm + 16, bP + boff + 16);
        cpa16(st + B_OFF + rSm + 32, bP + boff + 32);
        cpa16(st + B_OFF + rSm + 48, bP + boff + 48);
    };

    const uint32_t a_lm = (uint32_t)((wm * 32 + (lane & 15)) * APITCH + (lane >> 4) * 16);
    const uint32_t b_lm = (uint32_t)(B_OFF
        + (wn * 64 + ((lane >> 4) & 1) * 8 + (lane & 7)) * APITCH + ((lane >> 3) & 1) * 16);

    float acc[2][8][4];
    #pragma unroll
    for (int i = 0; i < 2; i++)
        #pragma unroll
        for (int j = 0; j < 8; j++)
            #pragma unroll
            for (int q = 0; q < 4; q++) acc[i][j][q] = 0.f;

    issue(0); CPA_COMMIT();
    issue(1); CPA_COMMIT();

    for (int ck = 0; ck < 16; ck++) {
        if (ck + 1 < 16) CPA_WAITG(1); else CPA_WAITG(0);
        __syncthreads();
        if (ck + 2 < 16) { issue(ck + 2); CPA_COMMIT(); }

        // timed L2 prefetch of epilogue operands (~10us before use; no ordering semantics)
        if (ck == 12) {
            #pragma unroll
            for (int i = 0; i < 2; i++) {
                const int idx = tid + i * 256;               // 0..511 lines of g_acc tile
                const int m = idx >> 2, so = (idx >> 1) & 1, l = idx & 1;
                l2pf((const char*)(g_acc
                      + ((size_t)(base_s[m] + (nb * 2 + so) * 64)) * 64) + l * 128);
            }
        }
        if (ck == 14) {
            const int h0p = (bx << 1) & 15, d_p = (bx >> 3) & 15, bbp = bx >> 7;
            #pragma unroll
            for (int i = 0; i < 2; i++) {
                const int idx = tid + i * 256;               // 0..511 lines of X region
                const int c = idx >> 3, hh = (idx >> 2) & 1, wn2 = (idx >> 1) & 1, l = idx & 1;
                const size_t off = (size_t)bbp * 16777216 + (size_t)c * 262144
                                 + d_p * 16384 + (h0p + hh) * 1024 + (nb * 2 + wn2) * 64;
                l2pf((const char*)(X + off) + l * 128);
            }
        }

        const uint32_t st = sb + (uint32_t)((ck % 3) * STAGE_B);
        #pragma unroll
        for (int ks = 0; ks < 4; ks++) {
            const uint32_t ko = (uint32_t)(ks * 32);
            uint32_t ah[2][4], br[4];
            ldsm4(ah[0], st + a_lm + ko);
            ldsm4(ah[1], st + a_lm + 16 * APITCH + ko);
            #pragma unroll
            for (int ntp = 0; ntp < 4; ntp++) {
                ldsm4(br, st + b_lm + ntp * 16 * APITCH + ko);
                mma16816(acc[0][2*ntp],   ah[0], br);
                mma16816(acc[0][2*ntp+1], ah[0], br + 2);
                mma16816(acc[1][2*ntp],   ah[1], br);
                mma16816(acc[1][2*ntp+1], ah[1], br + 2);
            }
        }
    }

    float* Cs = (float*)dsm;
    __syncthreads();
    {
        const int r0 = lane >> 2, cp = (lane & 3) * 2;
        #pragma unroll
        for (int mt = 0; mt < 2; mt++) {
            const int ml = wm * 32 + mt * 16 + r0;
            const size_t row0 = (size_t)(base_s[ml]     + (nb * 2 + wn) * 64);
            const size_t row1 = (size_t)(base_s[ml + 8] + (nb * 2 + wn) * 64);
            #pragma unroll
            for (int nt = 0; nt < 8; nt++) {
                const int c = nt * 8 + cp;
                const float2 g0 = *(const float2*)(g_acc + row0 * 64 + c);
                const float2 g1 = *(const float2*)(g_acc + row1 * 64 + c);
                const float bxv = bias_s[wn * 64 + c], byv = bias_s[wn * 64 + c + 1];
                Cs[ml * CS_PITCH + wn * 64 + c]           = acc[mt][nt][0] + bxv + g0.x;
                Cs[ml * CS_PITCH + wn * 64 + c + 1]       = acc[mt][nt][1] + byv + g0.y;
                Cs[(ml + 8) * CS_PITCH + wn * 64 + c]     = acc[mt][nt][2] + bxv + g1.x;
                Cs[(ml + 8) * CS_PITCH + wn * 64 + c + 1] = acc[mt][nt][3] + byv + g1.y;
            }
        }
    }
    __syncthreads();

    const int h0 = (bx << 1) & 15, d_ = (bx >> 3) & 15, bb = bx >> 7;
    #pragma unroll 4
    for (int it = 0; it < 32; it++) {
        const int ri = it * 8 + wid;
        const int c = ri & 63, hh = (ri >> 6) & 1, wn2 = ri >> 7;
        const size_t off = (size_t)bb * 16777216 + (size_t)c * 262144
                         + d_ * 16384 + (h0 + hh) * 1024 + (nb * 2 + wn2) * 64;
        #pragma unroll
        for (int ps = 0; ps < 2; ps++) {
            const int pqr = ps * 32 + lane;
            float a = Cs[(hh * 64 + pqr) * CS_PITCH + wn2 * 64 + c];
            a = (a > 0.f ? a : 0.01f * a);
            Y[off + pqr] = X[off + pqr] + a;
        }
    }
}

extern "C" void kernel_launch(void* const* d_in, const int* in_sizes, int n_in,
                              void* d_out, int out_size)
{
    const float* x    = (const float*)d_in[0];
    const float* w_d  = (const float*)d_in[1];
    const float* b_d  = (const float*)d_in[2];
    const float* w_h  = (const float*)d_in[3];
    const float* b_h  = (const float*)d_in[4];
    const float* w_w  = (const float*)d_in[5];
    const float* b_w  = (const float*)d_in[6];
    const float* w_pd = (const float*)d_in[7];
    const float* b_pd = (const float*)d_in[8];
    const float* w_ph = (const float*)d_in[9];
    const float* b_ph = (const float*)d_in[10];
    const float* w_pw = (const float*)d_in[11];
    const float* b_pw = (const float*)d_in[12];

    cudaFuncSetAttribute(patch_fused,   cudaFuncAttributeMaxDynamicSharedMemorySize, PF_DYN);
    cudaFuncSetAttribute(images_dh,     cudaFuncAttributeMaxDynamicSharedMemorySize, DYN_SMEM);
    cudaFuncSetAttribute(image_w_final, cudaFuncAttributeMaxDynamicSharedMemorySize, DYN_SMEM);

    prep_all<<<12032, 256>>>(x, w_d, w_h, w_w, w_pd, w_ph, w_pw);
    patch_fused<<<dim3(64, 32), 256, PF_DYN>>>(b_pd, b_ph, b_pw);
    images_dh<<<4096, 256, DYN_SMEM>>>(b_d, b_h);
    image_w_final<<<dim3(8, 256), 256, DYN_SMEM>>>(x, (float*)d_out, b_w);
}

// round 15
// speedup vs baseline: 1.0466x; 1.0466x over previous
#include <cuda_runtime.h>
#include <cuda_fp16.h>
#include <cstdint>

#define TOTAL_ELEMS 33554432

__device__ __align__(128) float g_acc[TOTAL_ELEMS];
__device__ __align__(128) __half g_xhi[TOTAL_ELEMS];
__device__ __align__(128) __half g_whi[3342336];

// ---- image GEMM stage: A 128x144B | B 128x144B (BK=64) ----
#define APITCH 144
#define B_OFF  18432
#define STAGE_B 36864
#define DYN_SMEM (3 * STAGE_B)      // 110592; 2 CTAs/SM

// ---- patch stage: A 256x80B | B 64x80B (BK=32), 4 stages ----
#define PF_BOFF 20480
#define PF_STG  25600
#define PF_DYN  (4 * PF_STG)        // 102400; 2 CTAs/SM

#define CS_PITCH 133

__device__ __forceinline__ uint32_t smem_u32(const void* p) {
    uint32_t a;
    asm("{ .reg .u64 t; cvta.to.shared.u64 t, %1; cvt.u32.u64 %0, t; }" : "=r"(a) : "l"(p));
    return a;
}
__device__ __forceinline__ void ldsm4(uint32_t* r, uint32_t a) {
    asm volatile("ldmatrix.sync.aligned.m8n8.x4.shared.b16 {%0,%1,%2,%3}, [%4];"
        : "=r"(r[0]), "=r"(r[1]), "=r"(r[2]), "=r"(r[3]) : "r"(a));
}
__device__ __forceinline__ void mma16816(float* d, const uint32_t* a, const uint32_t* b) {
    asm volatile("mma.sync.aligned.m16n8k16.row.col.f32.f16.f16.f32 "
        "{%0,%1,%2,%3}, {%4,%5,%6,%7}, {%8,%9}, {%0,%1,%2,%3};"
        : "+f"(d[0]), "+f"(d[1]), "+f"(d[2]), "+f"(d[3])
        : "r"(a[0]), "r"(a[1]), "r"(a[2]), "r"(a[3]), "r"(b[0]), "r"(b[1]));
}
__device__ __forceinline__ void cpa16(uint32_t s, const void* g) {
    asm volatile("cp.async.cg.shared.global [%0], [%1], 16;" :: "r"(s), "l"(g));
}
__device__ __forceinline__ void red_add(float* p, float v) {
    asm volatile("red.global.add.f32 [%0], %1;" :: "l"(p), "f"(v) : "memory");
}
#define CPA_COMMIT() asm volatile("cp.async.commit_group;" ::: "memory")
#define CPA_WAITG(k) asm volatile("cp.async.wait_group %0;" :: "n"(k) : "memory")

// ========= prep_all: CTAs 0..8191 = X->fp16 permute; 8192.. = W->fp16 =========
__global__ __launch_bounds__(256) void prep_all(
    const float* __restrict__ X,
    const float* __restrict__ w_d, const float* __restrict__ w_h,
    const float* __restrict__ w_w, const float* __restrict__ w_pd,
    const float* __restrict__ w_ph, const float* __restrict__ w_pw)
{
    const int t = threadIdx.x;
    if (blockIdx.x < 8192) {
        __shared__ float ts[64][65];
        const int b = blockIdx.x >> 12, sblk = blockIdx.x & 4095;
        const size_t s0 = (size_t)sblk * 64;
        const int sl = t & 63, ch = t >> 6;
        const float* xp = X + (size_t)b * 64 * 262144 + s0;
        #pragma unroll
        for (int i = 0; i < 16; i++) {
            const int c = ch + i * 4;
            ts[sl][c] = xp[(size_t)c * 262144 + sl];
        }
        __syncthreads();
        const int srow = t >> 2, sub = t & 3;
        const size_t row = (size_t)b * 262144 + s0 + srow;
        __half* hp = g_xhi + row * 64 + sub * 16;
        #pragma unroll
        for (int j = 0; j < 16; j++)
            hp[j] = __float2half(ts[srow][sub * 16 + j]);
    } else {
        const int b = blockIdx.x - 8192;
        const float* W; int woff, n, row;
        if (b < 3072) {
            const int op = b >> 10; row = b & 1023; n = 1024; woff = op * 1048576;
            W = (op == 0) ? w_d : (op == 1) ? w_h : w_w;
        } else {
            const int u = b - 3072;
            const int op = u >> 8; row = u & 255; n = 256; woff = 3145728 + op * 65536;
            W = (op == 0) ? w_pd : (op == 1) ? w_ph : w_pw;
        }
        const float* wp = W + (size_t)row * n;
        __half* hp = g_whi + woff + (size_t)row * n;
        for (int c = t; c < n; c += 256)
            hp[c] = __float2half(wp[c]);
    }
}

// ========== patch_fused: 3 patch ops, 256m x 64n, K=768, plain stores to g_acc ==========
__global__ __launch_bounds__(256, 2)
void patch_fused(const float* __restrict__ b_pd, const float* __restrict__ b_ph,
                 const float* __restrict__ b_pw)
{
    extern __shared__ __align__(16) char dsm[];
    __shared__ int base_sh[256];
    __shared__ float bias_sh[64];
    __shared__ int c0_s[3], step_s[3];
    __shared__ long wb_s[3];

    const int tid = threadIdx.x, lane = tid & 31, wid = tid >> 5;
    const int pqr = blockIdx.x, j2 = blockIdx.y;
    const int p = pqr >> 4, q = (pqr >> 2) & 3, r = pqr & 3;

    base_sh[tid] = (tid >> 7) * 262144 + (j2 * 128 + (tid & 127)) * 64;
    if (tid < 64)
        bias_sh[tid] = __ldg(b_pd + p * 64 + tid) + __ldg(b_ph + q * 64 + tid)
                     + __ldg(b_pw + r * 64 + tid);
    if (tid == 0) {
        c0_s[0] = q * 4 + r;      step_s[0] = 16;
        c0_s[1] = p * 16 + r;     step_s[1] = 4;
        c0_s[2] = p * 16 + q * 4; step_s[2] = 1;
        wb_s[0] = (long)(3145728 + p * 16384) * 2;
        wb_s[1] = (long)(3211264 + q * 16384) * 2;
        wb_s[2] = (long)(3276800 + r * 16384) * 2;
    }
    __syncthreads();

    const uint32_t sb = smem_u32(dsm);
    const int myrow = base_sh[tid];
    const uint32_t aSm = (uint32_t)(tid * 80);
    const uint32_t bSm = (uint32_t)(PF_BOFF + (tid >> 2) * 80 + (tid & 3) * 16);
    const long bRow = (long)(tid >> 2) * 512 + (tid & 3) * 16;

    auto issue = [&](int ck) {
        const int op = ck >> 3, s32 = ck & 7, s = s32 >> 1, half = s32 & 1;
        const uint32_t st = sb + (uint32_t)((ck & 3) * PF_STG);
        const char* ga = (const char*)g_xhi
            + ((size_t)(myrow + c0_s[op] + s * step_s[op])) * 128 + half * 64;
        cpa16(st + aSm,      ga);
        cpa16(st + aSm + 16, ga + 16);
        cpa16(st + aSm + 32, ga + 32);
        cpa16(st + aSm + 48, ga + 48);
        const char* gb = (const char*)g_whi + wb_s[op] + bRow + s * 128 + half * 64;
        cpa16(st + bSm, gb);
    };

    const uint32_t a_lm = (uint32_t)((wid * 32 + (lane & 15)) * 80 + (lane >> 4) * 16);
    const uint32_t b_lm = (uint32_t)(PF_BOFF
        + (((lane >> 4) & 1) * 8 + (lane & 7)) * 80 + ((lane >> 3) & 1) * 16);

    float acc[2][8][4];
    #pragma unroll
    for (int i = 0; i < 2; i++)
        #pragma unroll
        for (int j = 0; j < 8; j++)
            #pragma unroll
            for (int u = 0; u < 4; u++) acc[i][j][u] = 0.f;

    issue(0); CPA_COMMIT();
    issue(1); CPA_COMMIT();
    issue(2); CPA_COMMIT();

    for (int ck = 0; ck < 24; ck++) {
        if (ck + 1 < 24) CPA_WAITG(2); else CPA_WAITG(0);
        __syncthreads();
        if (ck + 3 < 24) { issue(ck + 3); CPA_COMMIT(); }

        const uint32_t st = sb + (uint32_t)((ck & 3) * PF_STG);
        #pragma unroll
        for (int ks = 0; ks < 2; ks++) {
            const uint32_t ko = (uint32_t)(ks * 32);
            uint32_t ah[2][4], br[4];
            ldsm4(ah[0], st + a_lm + ko);
            ldsm4(ah[1], st + a_lm + 16 * 80 + ko);
            #pragma unroll
            for (int ntp = 0; ntp < 4; ntp++) {
                ldsm4(br, st + b_lm + ntp * 16 * 80 + ko);
                mma16816(acc[0][2*ntp],   ah[0], br);
                mma16816(acc[0][2*ntp+1], ah[0], br + 2);
                mma16816(acc[1][2*ntp],   ah[1], br);
                mma16816(acc[1][2*ntp+1], ah[1], br + 2);
            }
        }
    }

    {
        const int r0 = lane >> 2, cp = (lane & 3) * 2;
        #pragma unroll
        for (int mt = 0; mt < 2; mt++) {
            const int m0 = wid * 32 + mt * 16 + r0;
            const size_t o0 = ((size_t)(base_sh[m0]     + pqr)) * 64;
            const size_t o1 = ((size_t)(base_sh[m0 + 8] + pqr)) * 64;
            #pragma unroll
            for (int nt = 0; nt < 8; nt++) {
                const int c = nt * 8 + cp;
                const float bx = bias_sh[c], by = bias_sh[c + 1];
                *(float2*)(g_acc + o0 + c) = make_float2(acc[mt][nt][0] + bx,
                                                         acc[mt][nt][1] + by);
                *(float2*)(g_acc + o1 + c) = make_float2(acc[mt][nt][2] + bx,
                                                         acc[mt][nt][3] + by);
            }
        }
    }
}

// ===== images d (0..2047) + h (2048..4095): 128m x 128n BK=64, red.add epilogue =====
__global__ __launch_bounds__(256, 2)
void images_dh(const float* __restrict__ b_d, const float* __restrict__ b_h)
{
    extern __shared__ __align__(16) char dsm[];
    __shared__ int base_sh[128];

    const int tid = threadIdx.x, lane = tid & 31, wid = tid >> 5;
    const uint32_t sb = smem_u32(dsm);
    const int bi = blockIdx.x;
    const int op = bi >> 11, tt = bi & 2047;
    const int nb = tt & 7, bx = tt >> 3;
    const int wm = wid & 3, wn = wid >> 2;
    const int woff = op ? 1048576 : 0;
    const int str_sp = op ? 1024 : 16384;
    const float* Bias = op ? b_h : b_d;

    if (tid < 128) {
        const int m = bx * 128 + tid;
        base_sh[tid] = op
            ? ((m & 1023) + ((m >> 10) & 15) * 16384 + (m >> 14) * 262144)
            : ((m & 16383) + (m >> 14) * 262144);
    }
    __syncthreads();

    const int row = tid >> 1;
    const int half = (tid & 1) * 64;
    const int aBase = base_sh[row];
    const char* aP = (const char*)g_xhi;
    const char* bP = (const char*)(g_whi + woff) + ((size_t)(nb * 128 + row)) * 2048 + half;
    const uint32_t rSm = (uint32_t)(row * APITCH + half);

    auto issue = [&](int ck) {
        const uint32_t st = sb + (uint32_t)((ck % 3) * STAGE_B);
        const size_t aoff = ((size_t)(aBase + ck * str_sp)) * 128 + half;
        cpa16(st + rSm,      aP + aoff);
        cpa16(st + rSm + 16, aP + aoff + 16);
        cpa16(st + rSm + 32, aP + aoff + 32);
        cpa16(st + rSm + 48, aP + aoff + 48);
        const size_t boff = (size_t)ck * 128;
        cpa16(st + B_OFF + rSm,      bP + boff);
        cpa16(st + B_OFF + rSm + 16, bP + boff + 16);
        cpa16(st + B_OFF + rSm + 32, bP + boff + 32);
        cpa16(st + B_OFF + rSm + 48, bP + boff + 48);
    };

    const uint32_t a_lm = (uint32_t)((wm * 32 + (lane & 15)) * APITCH + (lane >> 4) * 16);
    const uint32_t b_lm = (uint32_t)(B_OFF
        + (wn * 64 + ((lane >> 4) & 1) * 8 + (lane & 7)) * APITCH + ((lane >> 3) & 1) * 16);

    float acc[2][8][4];
    #pragma unroll
    for (int i = 0; i < 2; i++)
        #pragma unroll
        for (int j = 0; j < 8; j++)
            #pragma unroll
            for (int q = 0; q < 4; q++) acc[i][j][q] = 0.f;

    issue(0); CPA_COMMIT();
    issue(1); CPA_COMMIT();

    for (int ck = 0; ck < 16; ck++) {
        if (ck + 1 < 16) CPA_WAITG(1); else CPA_WAITG(0);
        __syncthreads();
        if (ck + 2 < 16) { issue(ck + 2); CPA_COMMIT(); }

        const uint32_t st = sb + (uint32_t)((ck % 3) * STAGE_B);
        #pragma unroll
        for (int ks = 0; ks < 4; ks++) {
            const uint32_t ko = (uint32_t)(ks * 32);
            uint32_t ah[2][4], br[4];
            ldsm4(ah[0], st + a_lm + ko);
            ldsm4(ah[1], st + a_lm + 16 * APITCH + ko);
            #pragma unroll
            for (int ntp = 0; ntp < 4; ntp++) {
                ldsm4(br, st + b_lm + ntp * 16 * APITCH + ko);
                mma16816(acc[0][2*ntp],   ah[0], br);
                mma16816(acc[0][2*ntp+1], ah[0], br + 2);
                mma16816(acc[1][2*ntp],   ah[1], br);
                mma16816(acc[1][2*ntp+1], ah[1], br + 2);
            }
        }
    }

    {
        const int s_out = nb * 2 + wn;
        const int r0 = lane >> 2, cp = (lane & 3) * 2;
        #pragma unroll
        for (int mt = 0; mt < 2; mt++) {
            const int ml = wm * 32 + mt * 16 + r0;
            const size_t row0 = (size_t)(base_sh[ml]     + s_out * str_sp);
            const size_t row1 = (size_t)(base_sh[ml + 8] + s_out * str_sp);
            #pragma unroll
            for (int nt = 0; nt < 8; nt++) {
                const int o = nb * 128 + wn * 64 + nt * 8 + cp;
                const int c = nt * 8 + cp;
                const float2 bv = __ldg((const float2*)(Bias + o));
                red_add(g_acc + row0 * 64 + c,     acc[mt][nt][0] + bv.x);
                red_add(g_acc + row0 * 64 + c + 1, acc[mt][nt][1] + bv.y);
                red_add(g_acc + row1 * 64 + c,     acc[mt][nt][2] + bv.x);
                red_add(g_acc + row1 * 64 + c + 1, acc[mt][nt][3] + bv.y);
            }
        }
    }
}

// ==== image op w + final: reads g_acc, adds own result+bias, leaky+residual -> Y ====
__global__ __launch_bounds__(256, 2)
void image_w_final(const float* __restrict__ X, float* __restrict__ Y,
                   const float* __restrict__ b_w)
{
    extern __shared__ __align__(16) char dsm[];
    __shared__ int base_s[128];
    __shared__ float bias_s[128];

    const int tid = threadIdx.x;
    const int lane = tid & 31, wid = tid >> 5;
    const int nb = blockIdx.x, bx = blockIdx.y;
    const int wm = wid & 3, wn = wid >> 2;
    const uint32_t sb = smem_u32(dsm);

    if (tid < 128) {
        const int m = bx * 128 + tid;
        base_s[tid] = (m & 63) + ((m >> 6) & 15) * 1024
                    + ((m >> 10) & 15) * 16384 + (m >> 14) * 262144;
        bias_s[tid] = __ldg(b_w + (nb * 2 + (tid >> 6)) * 64 + (tid & 63));
    }
    __syncthreads();

    const int row = tid >> 1;
    const int half = (tid & 1) * 64;
    const int aBase = base_s[row];
    const char* aP = (const char*)g_xhi;
    const char* bP = (const char*)(g_whi + 2097152) + ((size_t)(nb * 128 + row)) * 2048 + half;
    const uint32_t rSm = (uint32_t)(row * APITCH + half);

    auto issue = [&](int ck) {
        const uint32_t st = sb + (uint32_t)((ck % 3) * STAGE_B);
        const size_t aoff = ((size_t)(aBase + ck * 64)) * 128 + half;
        cpa16(st + rSm,      aP + aoff);
        cpa16(st + rSm + 16, aP + aoff + 16);
        cpa16(st + rSm + 32, aP + aoff + 32);
        cpa16(st + rSm + 48, aP + aoff + 48);
        const size_t boff = (size_t)ck * 128;
        cpa16(st + B_OFF + rSm,      bP + boff);
        cpa16(st + B_OFF + rSm + 16, bP + boff + 16);
        cpa16(st + B_OFF + rSm + 32, bP + boff + 32);
        cpa16(st + B_OFF + rSm + 48, bP + boff + 48);
    };

    const uint32_t a_lm = (uint32_t)((wm * 32 + (lane & 15)) * APITCH + (lane >> 4) * 16);
    const uint32_t b_lm = (uint32_t)(B_OFF
        + (wn * 64 + ((lane >> 4) & 1) * 8 + (lane & 7)) * APITCH + ((lane >> 3) & 1) * 16);

    float acc[2][8][4];
    #pragma unroll
    for (int i = 0; i < 2; i++)
        #pragma unroll
        for (int j = 0; j < 8; j++)
            #pragma unroll
            for (int q = 0; q < 4; q++) acc[i][j][q] = 0.f;

    issue(0); CPA_COMMIT();
    issue(1); CPA_COMMIT();

    for (int ck = 0; ck < 16; ck++) {
        if (ck + 1 < 16) CPA_WAITG(1); else CPA_WAITG(0);
        __syncthreads();
        if (ck + 2 < 16) { issue(ck + 2); CPA_COMMIT(); }

        const uint32_t st = sb + (uint32_t)((ck % 3) * STAGE_B);
        #pragma unroll
        for (int ks = 0; ks < 4; ks++) {
            const uint32_t ko = (uint32_t)(ks * 32);
            uint32_t ah[2][4], br[4];
            ldsm4(ah[0], st + a_lm + ko);
            ldsm4(ah[1], st + a_lm + 16 * APITCH + ko);
            #pragma unroll
            for (int ntp = 0; ntp < 4; ntp++) {
                ldsm4(br, st + b_lm + ntp * 16 * APITCH + ko);
                mma16816(acc[0][2*ntp],   ah[0], br);
                mma16816(acc[0][2*ntp+1], ah[0], br + 2);
                mma16816(acc[1][2*ntp],   ah[1], br);
                mma16816(acc[1][2*ntp+1], ah[1], br + 2);
            }
        }
    }

    float* Cs = (float*)dsm;
    __syncthreads();
    {
        const int r0 = lane >> 2, cp = (lane & 3) * 2;
        #pragma unroll
        for (int mt = 0; mt < 2; mt++) {
            const int ml = wm * 32 + mt * 16 + r0;
            const size_t row0 = (size_t)(base_s[ml]     + (nb * 2 + wn) * 64);
            const size_t row1 = (size_t)(base_s[ml + 8] + (nb * 2 + wn) * 64);
            #pragma unroll
            for (int nt = 0; nt < 8; nt++) {
                const int c = nt * 8 + cp;
                const float2 g0 = *(const float2*)(g_acc + row0 * 64 + c);
                const float2 g1 = *(const float2*)(g_acc + row1 * 64 + c);
                const float bxv = bias_s[wn * 64 + c], byv = bias_s[wn * 64 + c + 1];
                Cs[ml * CS_PITCH + wn * 64 + c]           = acc[mt][nt][0] + bxv + g0.x;
                Cs[ml * CS_PITCH + wn * 64 + c + 1]       = acc[mt][nt][1] + byv + g0.y;
                Cs[(ml + 8) * CS_PITCH + wn * 64 + c]     = acc[mt][nt][2] + bxv + g1.x;
                Cs[(ml + 8) * CS_PITCH + wn * 64 + c + 1] = acc[mt][nt][3] + byv + g1.y;
            }
        }
    }
    __syncthreads();

    const int h0 = (bx << 1) & 15, d_ = (bx >> 3) & 15, bb = bx >> 7;
    #pragma unroll 4
    for (int it = 0; it < 32; it++) {
        const int ri = it * 8 + wid;
        const int c = ri & 63, hh = (ri >> 6) & 1, wn2 = ri >> 7;
        const size_t off = (size_t)bb * 16777216 + (size_t)c * 262144
                         + d_ * 16384 + (h0 + hh) * 1024 + (nb * 2 + wn2) * 64;
        #pragma unroll
        for (int ps = 0; ps < 2; ps++) {
            const int pqr = ps * 32 + lane;
            float a = Cs[(hh * 64 + pqr) * CS_PITCH + wn2 * 64 + c];
            a = (a > 0.f ? a : 0.01f * a);
            Y[off + pqr] = X[off + pqr] + a;
        }
    }
}

extern "C" void kernel_launch(void* const* d_in, const int* in_sizes, int n_in,
                              void* d_out, int out_size)
{
    const float* x    = (const float*)d_in[0];
    const float* w_d  = (const float*)d_in[1];
    const float* b_d  = (const float*)d_in[2];
    const float* w_h  = (const float*)d_in[3];
    const float* b_h  = (const float*)d_in[4];
    const float* w_w  = (const float*)d_in[5];
    const float* b_w  = (const float*)d_in[6];
    const float* w_pd = (const float*)d_in[7];
    const float* b_pd = (const float*)d_in[8];
    const float* w_ph = (const float*)d_in[9];
    const float* b_ph = (const float*)d_in[10];
    const float* w_pw = (const float*)d_in[11];
    const float* b_pw = (const float*)d_in[12];

    cudaFuncSetAttribute(patch_fused,   cudaFuncAttributeMaxDynamicSharedMemorySize, PF_DYN);
    cudaFuncSetAttribute(images_dh,     cudaFuncAttributeMaxDynamicSharedMemorySize, DYN_SMEM);
    cudaFuncSetAttribute(image_w_final, cudaFuncAttributeMaxDynamicSharedMemorySize, DYN_SMEM);

    prep_all<<<12032, 256>>>(x, w_d, w_h, w_w, w_pd, w_ph, w_pw);
    patch_fused<<<dim3(64, 32), 256, PF_DYN>>>(b_pd, b_ph, b_pw);
    images_dh<<<4096, 256, DYN_SMEM>>>(b_d, b_h);
    image_w_final<<<dim3(8, 256), 256, DYN_SMEM>>>(x, (float*)d_out, b_w);
}

// round 16
// speedup vs baseline: 1.0473x; 1.0006x over previous
#include <cuda_runtime.h>
#include <cuda_fp16.h>
#include <cstdint>

#define TOTAL_ELEMS 33554432

__device__ __align__(128) float g_acc[TOTAL_ELEMS];
__device__ __align__(128) __half g_xhi[TOTAL_ELEMS];
__device__ __align__(128) __half g_whi[3342336];

// ---- image GEMM stage: A 128x144B | B 128x144B (BK=64) ----
#define APITCH 144
#define B_OFF  18432
#define STAGE_B 36864
#define DYN_SMEM (3 * STAGE_B)      // 110592; 2 CTAs/SM

// ---- patch stage: A 256x80B | B 64x80B (BK=32), 4 stages ----
#define PF_BOFF 20480
#define PF_STG  25600
#define PF_DYN  (4 * PF_STG)        // 102400; 2 CTAs/SM

#define CS_PITCH 133

__device__ __forceinline__ uint32_t smem_u32(const void* p) {
    uint32_t a;
    asm("{ .reg .u64 t; cvta.to.shared.u64 t, %1; cvt.u32.u64 %0, t; }" : "=r"(a) : "l"(p));
    return a;
}
__device__ __forceinline__ void ldsm4(uint32_t* r, uint32_t a) {
    asm volatile("ldmatrix.sync.aligned.m8n8.x4.shared.b16 {%0,%1,%2,%3}, [%4];"
        : "=r"(r[0]), "=r"(r[1]), "=r"(r[2]), "=r"(r[3]) : "r"(a));
}
__device__ __forceinline__ void mma16816(float* d, const uint32_t* a, const uint32_t* b) {
    asm volatile("mma.sync.aligned.m16n8k16.row.col.f32.f16.f16.f32 "
        "{%0,%1,%2,%3}, {%4,%5,%6,%7}, {%8,%9}, {%0,%1,%2,%3};"
        : "+f"(d[0]), "+f"(d[1]), "+f"(d[2]), "+f"(d[3])
        : "r"(a[0]), "r"(a[1]), "r"(a[2]), "r"(a[3]), "r"(b[0]), "r"(b[1]));
}
__device__ __forceinline__ void cpa16(uint32_t s, const void* g) {
    asm volatile("cp.async.cg.shared.global [%0], [%1], 16;" :: "r"(s), "l"(g));
}
__device__ __forceinline__ void red_add(float* p, float v) {
    asm volatile("red.global.add.f32 [%0], %1;" :: "l"(p), "f"(v) : "memory");
}
__device__ __forceinline__ uint32_t pack2(float a, float b) {
    __half2 h = __floats2half2_rn(a, b);
    return *reinterpret_cast<uint32_t*>(&h);
}
#define CPA_COMMIT() asm volatile("cp.async.commit_group;" ::: "memory")
#define CPA_WAITG(k) asm volatile("cp.async.wait_group %0;" :: "n"(k) : "memory")

// ========= prep_all: CTAs 0..8191 = X->fp16 permute (vectorized); 8192.. = W->fp16 =========
__global__ __launch_bounds__(256) void prep_all(
    const float* __restrict__ X,
    const float* __restrict__ w_d, const float* __restrict__ w_h,
    const float* __restrict__ w_w, const float* __restrict__ w_pd,
    const float* __restrict__ w_ph, const float* __restrict__ w_pw)
{
    const int t = threadIdx.x;
    if (blockIdx.x < 8192) {
        __shared__ float ts[64][65];
        const int b = blockIdx.x >> 12, sblk = blockIdx.x & 4095;
        const size_t s0 = (size_t)sblk * 64;
        const int sl = t & 63, ch = t >> 6;
        const float* xp = X + (size_t)b * 64 * 262144 + s0;
        #pragma unroll
        for (int i = 0; i < 16; i++) {
            const int c = ch + i * 4;
            ts[sl][c] = xp[(size_t)c * 262144 + sl];
        }
        __syncthreads();
        const int srow = t >> 2, sub = t & 3;
        const size_t row = (size_t)b * 262144 + s0 + srow;
        const float* src = &ts[srow][sub * 16];
        uint4 v0, v1;
        v0.x = pack2(src[0],  src[1]);  v0.y = pack2(src[2],  src[3]);
        v0.z = pack2(src[4],  src[5]);  v0.w = pack2(src[6],  src[7]);
        v1.x = pack2(src[8],  src[9]);  v1.y = pack2(src[10], src[11]);
        v1.z = pack2(src[12], src[13]); v1.w = pack2(src[14], src[15]);
        uint4* hp = (uint4*)(g_xhi + row * 64 + sub * 16);
        hp[0] = v0;
        hp[1] = v1;
    } else {
        const int b = blockIdx.x - 8192;
        const float* W; int woff, n, row;
        if (b < 3072) {
            const int op = b >> 10; row = b & 1023; n = 1024; woff = op * 1048576;
            W = (op == 0) ? w_d : (op == 1) ? w_h : w_w;
        } else {
            const int u = b - 3072;
            const int op = u >> 8; row = u & 255; n = 256; woff = 3145728 + op * 65536;
            W = (op == 0) ? w_pd : (op == 1) ? w_ph : w_pw;
        }
        const float* wp = W + (size_t)row * n;
        __half* hp = g_whi + woff + (size_t)row * n;
        for (int c4 = t * 4; c4 < n; c4 += 1024) {
            const float4 v = *(const float4*)(wp + c4);
            uint2 o;
            o.x = pack2(v.x, v.y);
            o.y = pack2(v.z, v.w);
            *(uint2*)(hp + c4) = o;
        }
    }
}

// ========== patch_fused: 3 patch ops, 256m x 64n, K=768, plain stores to g_acc ==========
__global__ __launch_bounds__(256, 2)
void patch_fused(const float* __restrict__ b_pd, const float* __restrict__ b_ph,
                 const float* __restrict__ b_pw)
{
    extern __shared__ __align__(16) char dsm[];
    __shared__ int base_sh[256];
    __shared__ float bias_sh[64];
    __shared__ int c0_s[3], step_s[3];
    __shared__ long wb_s[3];

    const int tid = threadIdx.x, lane = tid & 31, wid = tid >> 5;
    const int pqr = blockIdx.x, j2 = blockIdx.y;
    const int p = pqr >> 4, q = (pqr >> 2) & 3, r = pqr & 3;

    base_sh[tid] = (tid >> 7) * 262144 + (j2 * 128 + (tid & 127)) * 64;
    if (tid < 64)
        bias_sh[tid] = __ldg(b_pd + p * 64 + tid) + __ldg(b_ph + q * 64 + tid)
                     + __ldg(b_pw + r * 64 + tid);
    if (tid == 0) {
        c0_s[0] = q * 4 + r;      step_s[0] = 16;
        c0_s[1] = p * 16 + r;     step_s[1] = 4;
        c0_s[2] = p * 16 + q * 4; step_s[2] = 1;
        wb_s[0] = (long)(3145728 + p * 16384) * 2;
        wb_s[1] = (long)(3211264 + q * 16384) * 2;
        wb_s[2] = (long)(3276800 + r * 16384) * 2;
    }
    __syncthreads();

    const uint32_t sb = smem_u32(dsm);
    const int myrow = base_sh[tid];
    const uint32_t aSm = (uint32_t)(tid * 80);
    const uint32_t bSm = (uint32_t)(PF_BOFF + (tid >> 2) * 80 + (tid & 3) * 16);
    const long bRow = (long)(tid >> 2) * 512 + (tid & 3) * 16;

    auto issue = [&](int ck) {
        const int op = ck >> 3, s32 = ck & 7, s = s32 >> 1, half = s32 & 1;
        const uint32_t st = sb + (uint32_t)((ck & 3) * PF_STG);
        const char* ga = (const char*)g_xhi
            + ((size_t)(myrow + c0_s[op] + s * step_s[op])) * 128 + half * 64;
        cpa16(st + aSm,      ga);
        cpa16(st + aSm + 16, ga + 16);
        cpa16(st + aSm + 32, ga + 32);
        cpa16(st + aSm + 48, ga + 48);
        const char* gb = (const char*)g_whi + wb_s[op] + bRow + s * 128 + half * 64;
        cpa16(st + bSm, gb);
    };

    const uint32_t a_lm = (uint32_t)((wid * 32 + (lane & 15)) * 80 + (lane >> 4) * 16);
    const uint32_t b_lm = (uint32_t)(PF_BOFF
        + (((lane >> 4) & 1) * 8 + (lane & 7)) * 80 + ((lane >> 3) & 1) * 16);

    float acc[2][8][4];
    #pragma unroll
    for (int i = 0; i < 2; i++)
        #pragma unroll
        for (int j = 0; j < 8; j++)
            #pragma unroll
            for (int u = 0; u < 4; u++) acc[i][j][u] = 0.f;

    issue(0); CPA_COMMIT();
    issue(1); CPA_COMMIT();
    issue(2); CPA_COMMIT();

    for (int ck = 0; ck < 24; ck++) {
        if (ck + 1 < 24) CPA_WAITG(2); else CPA_WAITG(0);
        __syncthreads();
        if (ck + 3 < 24) { issue(ck + 3); CPA_COMMIT(); }

        const uint32_t st = sb + (uint32_t)((ck & 3) * PF_STG);
        #pragma unroll
        for (int ks = 0; ks < 2; ks++) {
            const uint32_t ko = (uint32_t)(ks * 32);
            uint32_t ah[2][4], br[4];
            ldsm4(ah[0], st + a_lm + ko);
            ldsm4(ah[1], st + a_lm + 16 * 80 + ko);
            #pragma unroll
            for (int ntp = 0; ntp < 4; ntp++) {
                ldsm4(br, st + b_lm + ntp * 16 * 80 + ko);
                mma16816(acc[0][2*ntp],   ah[0], br);
                mma16816(acc[0][2*ntp+1], ah[0], br + 2);
                mma16816(acc[1][2*ntp],   ah[1], br);
                mma16816(acc[1][2*ntp+1], ah[1], br + 2);
            }
        }
    }

    {
        const int r0 = lane >> 2, cp = (lane & 3) * 2;
        #pragma unroll
        for (int mt = 0; mt < 2; mt++) {
            const int m0 = wid * 32 + mt * 16 + r0;
            const size_t o0 = ((size_t)(base_sh[m0]     + pqr)) * 64;
            const size_t o1 = ((size_t)(base_sh[m0 + 8] + pqr)) * 64;
            #pragma unroll
            for (int nt = 0; nt < 8; nt++) {
                const int c = nt * 8 + cp;
                const float bx = bias_sh[c], by = bias_sh[c + 1];
                *(float2*)(g_acc + o0 + c) = make_float2(acc[mt][nt][0] + bx,
                                                         acc[mt][nt][1] + by);
                *(float2*)(g_acc + o1 + c) = make_float2(acc[mt][nt][2] + bx,
                                                         acc[mt][nt][3] + by);
            }
        }
    }
}

// ===== images d (0..2047) + h (2048..4095): 128m x 128n BK=64, red.add epilogue =====
__global__ __launch_bounds__(256, 2)
void images_dh(const float* __restrict__ b_d, const float* __restrict__ b_h)
{
    extern __shared__ __align__(16) char dsm[];
    __shared__ int base_sh[128];

    const int tid = threadIdx.x, lane = tid & 31, wid = tid >> 5;
    const uint32_t sb = smem_u32(dsm);
    const int bi = blockIdx.x;
    const int op = bi >> 11, tt = bi & 2047;
    const int nb = tt & 7, bx = tt >> 3;
    const int wm = wid & 3, wn = wid >> 2;
    const int woff = op ? 1048576 : 0;
    const int str_sp = op ? 1024 : 16384;
    const float* Bias = op ? b_h : b_d;

    if (tid < 128) {
        const int m = bx * 128 + tid;
        base_sh[tid] = op
            ? ((m & 1023) + ((m >> 10) & 15) * 16384 + (m >> 14) * 262144)
            : ((m & 16383) + (m >> 14) * 262144);
    }
    __syncthreads();

    const int row = tid >> 1;
    const int half = (tid & 1) * 64;
    const int aBase = base_sh[row];
    const char* aP = (const char*)g_xhi;
    const char* bP = (const char*)(g_whi + woff) + ((size_t)(nb * 128 + row)) * 2048 + half;
    const uint32_t rSm = (uint32_t)(row * APITCH + half);

    auto issue = [&](int ck) {
        const uint32_t st = sb + (uint32_t)((ck % 3) * STAGE_B);
        const size_t aoff = ((size_t)(aBase + ck * str_sp)) * 128 + half;
        cpa16(st + rSm,      aP + aoff);
        cpa16(st + rSm + 16, aP + aoff + 16);
        cpa16(st + rSm + 32, aP + aoff + 32);
        cpa16(st + rSm + 48, aP + aoff + 48);
        const size_t boff = (size_t)ck * 128;
        cpa16(st + B_OFF + rSm,      bP + boff);
        cpa16(st + B_OFF + rSm + 16, bP + boff + 16);
        cpa16(st + B_OFF + rSm + 32, bP + boff + 32);
        cpa16(st + B_OFF + rSm + 48, bP + boff + 48);
    };

    const uint32_t a_lm = (uint32_t)((wm * 32 + (lane & 15)) * APITCH + (lane >> 4) * 16);
    const uint32_t b_lm = (uint32_t)(B_OFF
        + (wn * 64 + ((lane >> 4) & 1) * 8 + (lane & 7)) * APITCH + ((lane >> 3) & 1) * 16);

    float acc[2][8][4];
    #pragma unroll
    for (int i = 0; i < 2; i++)
        #pragma unroll
        for (int j = 0; j < 8; j++)
            #pragma unroll
            for (int q = 0; q < 4; q++) acc[i][j][q] = 0.f;

    issue(0); CPA_COMMIT();
    issue(1); CPA_COMMIT();

    for (int ck = 0; ck < 16; ck++) {
        if (ck + 1 < 16) CPA_WAITG(1); else CPA_WAITG(0);
        __syncthreads();
        if (ck + 2 < 16) { issue(ck + 2); CPA_COMMIT(); }

        const uint32_t st = sb + (uint32_t)((ck % 3) * STAGE_B);
        #pragma unroll
        for (int ks = 0; ks < 4; ks++) {
            const uint32_t ko = (uint32_t)(ks * 32);
            uint32_t ah[2][4], br[4];
            ldsm4(ah[0], st + a_lm + ko);
            ldsm4(ah[1], st + a_lm + 16 * APITCH + ko);
            #pragma unroll
            for (int ntp = 0; ntp < 4; ntp++) {
                ldsm4(br, st + b_lm + ntp * 16 * APITCH + ko);
                mma16816(acc[0][2*ntp],   ah[0], br);
                mma16816(acc[0][2*ntp+1], ah[0], br + 2);
                mma16816(acc[1][2*ntp],   ah[1], br);
                mma16816(acc[1][2*ntp+1], ah[1], br + 2);
            }
        }
    }

    {
        const int s_out = nb * 2 + wn;
        const int r0 = lane >> 2, cp = (lane & 3) * 2;
        #pragma unroll
        for (int mt = 0; mt < 2; mt++) {
            const int ml = wm * 32 + mt * 16 + r0;
            const size_t row0 = (size_t)(base_sh[ml]     + s_out * str_sp);
            const size_t row1 = (size_t)(base_sh[ml + 8] + s_out * str_sp);
            #pragma unroll
            for (int nt = 0; nt < 8; nt++) {
                const int o = nb * 128 + wn * 64 + nt * 8 + cp;
                const int c = nt * 8 + cp;
                const float2 bv = __ldg((const float2*)(Bias + o));
                red_add(g_acc + row0 * 64 + c,     acc[mt][nt][0] + bv.x);
                red_add(g_acc + row0 * 64 + c + 1, acc[mt][nt][1] + bv.y);
                red_add(g_acc + row1 * 64 + c,     acc[mt][nt][2] + bv.x);
                red_add(g_acc + row1 * 64 + c + 1, acc[mt][nt][3] + bv.y);
            }
        }
    }
}

// ==== image op w + final: reads g_acc, adds own result+bias, leaky+residual -> Y ====
__global__ __launch_bounds__(256, 2)
void image_w_final(const float* __restrict__ X, float* __restrict__ Y,
                   const float* __restrict__ b_w)
{
    extern __shared__ __align__(16) char dsm[];
    __shared__ int base_s[128];
    __shared__ float bias_s[128];

    const int tid = threadIdx.x;
    const int lane = tid & 31, wid = tid >> 5;
    const int nb = blockIdx.x, bx = blockIdx.y;
    const int wm = wid & 3, wn = wid >> 2;
    const uint32_t sb = smem_u32(dsm);

    if (tid < 128) {
        const int m = bx * 128 + tid;
        base_s[tid] = (m & 63) + ((m >> 6) & 15) * 1024
                    + ((m >> 10) & 15) * 16384 + (m >> 14) * 262144;
        bias_s[tid] = __ldg(b_w + (nb * 2 + (tid >> 6)) * 64 + (tid & 63));
    }
    __syncthreads();

    const int row = tid >> 1;
    const int half = (tid & 1) * 64;
    const int aBase = base_s[row];
    const char* aP = (const char*)g_xhi;
    const char* bP = (const char*)(g_whi + 2097152) + ((size_t)(nb * 128 + row)) * 2048 + half;
    const uint32_t rSm = (uint32_t)(row * APITCH + half);

    auto issue = [&](int ck) {
        const uint32_t st = sb + (uint32_t)((ck % 3) * STAGE_B);
        const size_t aoff = ((size_t)(aBase + ck * 64)) * 128 + half;
        cpa16(st + rSm,      aP + aoff);
        cpa16(st + rSm + 16, aP + aoff + 16);
        cpa16(st + rSm + 32, aP + aoff + 32);
        cpa16(st + rSm + 48, aP + aoff + 48);
        const size_t boff = (size_t)ck * 128;
        cpa16(st + B_OFF + rSm,      bP + boff);
        cpa16(st + B_OFF + rSm + 16, bP + boff + 16);
        cpa16(st + B_OFF + rSm + 32, bP + boff + 32);
        cpa16(st + B_OFF + rSm + 48, bP + boff + 48);
    };

    const uint32_t a_lm = (uint32_t)((wm * 32 + (lane & 15)) * APITCH + (lane >> 4) * 16);
    const uint32_t b_lm = (uint32_t)(B_OFF
        + (wn * 64 + ((lane >> 4) & 1) * 8 + (lane & 7)) * APITCH + ((lane >> 3) & 1) * 16);

    float acc[2][8][4];
    #pragma unroll
    for (int i = 0; i < 2; i++)
        #pragma unroll
        for (int j = 0; j < 8; j++)
            #pragma unroll
            for (int q = 0; q < 4; q++) acc[i][j][q] = 0.f;

    issue(0); CPA_COMMIT();
    issue(1); CPA_COMMIT();

    for (int ck = 0; ck < 16; ck++) {
        if (ck + 1 < 16) CPA_WAITG(1); else CPA_WAITG(0);
        __syncthreads();
        if (ck + 2 < 16) { issue(ck + 2); CPA_COMMIT(); }

        const uint32_t st = sb + (uint32_t)((ck % 3) * STAGE_B);
        #pragma unroll
        for (int ks = 0; ks < 4; ks++) {
            const uint32_t ko = (uint32_t)(ks * 32);
            uint32_t ah[2][4], br[4];
            ldsm4(ah[0], st + a_lm + ko);
            ldsm4(ah[1], st + a_lm + 16 * APITCH + ko);
            #pragma unroll
            for (int ntp = 0; ntp < 4; ntp++) {
                ldsm4(br, st + b_lm + ntp * 16 * APITCH + ko);
                mma16816(acc[0][2*ntp],   ah[0], br);
                mma16816(acc[0][2*ntp+1], ah[0], br + 2);
                mma16816(acc[1][2*ntp],   ah[1], br);
                mma16816(acc[1][2*ntp+1], ah[1], br + 2);
            }
        }
    }

    float* Cs = (float*)dsm;
    __syncthreads();
    {
        const int r0 = lane >> 2, cp = (lane & 3) * 2;
        #pragma unroll
        for (int mt = 0; mt < 2; mt++) {
            const int ml = wm * 32 + mt * 16 + r0;
            const size_t row0 = (size_t)(base_s[ml]     + (nb * 2 + wn) * 64);
            const size_t row1 = (size_t)(base_s[ml + 8] + (nb * 2 + wn) * 64);
            #pragma unroll
            for (int nt = 0; nt < 8; nt++) {
                const int c = nt * 8 + cp;
                const float2 g0 = *(const float2*)(g_acc + row0 * 64 + c);
                const float2 g1 = *(const float2*)(g_acc + row1 * 64 + c);
                const float bxv = bias_s[wn * 64 + c], byv = bias_s[wn * 64 + c + 1];
                Cs[ml * CS_PITCH + wn * 64 + c]           = acc[mt][nt][0] + bxv + g0.x;
                Cs[ml * CS_PITCH + wn * 64 + c + 1]       = acc[mt][nt][1] + byv + g0.y;
                Cs[(ml + 8) * CS_PITCH + wn * 64 + c]     = acc[mt][nt][2] + bxv + g1.x;
                Cs[(ml + 8) * CS_PITCH + wn * 64 + c + 1] = acc[mt][nt][3] + byv + g1.y;
            }
        }
    }
    __syncthreads();

    const int h0 = (bx << 1) & 15, d_ = (bx >> 3) & 15, bb = bx >> 7;
    #pragma unroll 4
    for (int it = 0; it < 32; it++) {
        const int ri = it * 8 + wid;
        const int c = ri & 63, hh = (ri >> 6) & 1, wn2 = ri >> 7;
        const size_t off = (size_t)bb * 16777216 + (size_t)c * 262144
                         + d_ * 16384 + (h0 + hh) * 1024 + (nb * 2 + wn2) * 64;
        #pragma unroll
        for (int ps = 0; ps < 2; ps++) {
            const int pqr = ps * 32 + lane;
            float a = Cs[(hh * 64 + pqr) * CS_PITCH + wn2 * 64 + c];
            a = (a > 0.f ? a : 0.01f * a);
            Y[off + pqr] = X[off + pqr] + a;
        }
    }
}

extern "C" void kernel_launch(void* const* d_in, const int* in_sizes, int n_in,
                              void* d_out, int out_size)
{
    const float* x    = (const float*)d_in[0];
    const float* w_d  = (const float*)d_in[1];
    const float* b_d  = (const float*)d_in[2];
    const float* w_h  = (const float*)d_in[3];
    const float* b_h  = (const float*)d_in[4];
    const float* w_w  = (const float*)d_in[5];
    const float* b_w  = (const float*)d_in[6];
    const float* w_pd = (const float*)d_in[7];
    const float* b_pd = (const float*)d_in[8];
    const float* w_ph = (const float*)d_in[9];
    const float* b_ph = (const float*)d_in[10];
    const float* w_pw = (const float*)d_in[11];
    const float* b_pw = (const float*)d_in[12];

    cudaFuncSetAttribute(patch_fused,   cudaFuncAttributeMaxDynamicSharedMemorySize, PF_DYN);
    cudaFuncSetAttribute(images_dh,     cudaFuncAttributeMaxDynamicSharedMemorySize, DYN_SMEM);
    cudaFuncSetAttribute(image_w_final, cudaFuncAttributeMaxDynamicSharedMemorySize, DYN_SMEM);

    prep_all<<<12032, 256>>>(x, w_d, w_h, w_w, w_pd, w_ph, w_pw);
    patch_fused<<<dim3(64, 32), 256, PF_DYN>>>(b_pd, b_ph, b_pw);
    images_dh<<<4096, 256, DYN_SMEM>>>(b_d, b_h);
    image_w_final<<<dim3(8, 256), 256, DYN_SMEM>>>(x, (float*)d_out, b_w);
}